// round 6
// baseline (speedup 1.0000x reference)
#include <cuda_runtime.h>
#include <cuda_bf16.h>
#include <cstdint>

#define Hh 128
#define Ww 256
#define HW (Hh*Ww)
#define NB 4
#define CIN 256
#define Tc 64
#define CCLS 19

// ---------------- scratch (allocation-free: __device__ globals) ----------------
// g_y: [nb][chunk16][pix][8 u32] ; chunk = out-ch/8, u32 = packed bf16 hi|lo per channel
__device__ __align__(16) uint32_t g_y[NB * 16 * HW * 8];
__device__ float    g_x[NB * Tc * HW];        // after BN+ReLU, channel-major (k3 input)
__device__ float    g_flow[2][NB * 2 * HW];   // partial flows (channel-split halves)
// weight fragments: [..][lane][4] u32 = {hi_j0, hi_j1, lo_j0, lo_j1}
__device__ __align__(16) uint32_t g_wd[2 * 16 * 8 * 32 * 4];   // 1x1: [wh][ks16][nf8][lane][4]
__device__ __align__(16) uint32_t g_wf[9 * 8 * 8 * 32 * 4];    // 3x3: [tap][ks8][nf8][lane][4]
__device__ float    g_bns[64], g_bnb[64];

// ---------------- helpers ----------------
__device__ __forceinline__ uint32_t smem_u32(const void* p) {
    uint32_t a;
    asm("{ .reg .u64 t; cvta.to.shared.u64 t, %1; cvt.u32.u64 %0, t; }" : "=r"(a) : "l"(p));
    return a;
}
__device__ __forceinline__ void cp_async16(uint32_t saddr, const void* g) {
    asm volatile("cp.async.cg.shared.global [%0], [%1], 16;" :: "r"(saddr), "l"(g));
}
__device__ __forceinline__ void cp_commit() { asm volatile("cp.async.commit_group;"); }
__device__ __forceinline__ void cp_wait0()  { asm volatile("cp.async.wait_group 0;"); }

__device__ __forceinline__ uint32_t split_pack(float v) {
    __nv_bfloat16 h = __float2bfloat16(v);
    float r = v - __bfloat162float(h);
    __nv_bfloat16 l = __float2bfloat16(r);
    return ((uint32_t)__bfloat16_as_ushort(h) << 16) | (uint32_t)__bfloat16_as_ushort(l);
}
__device__ __forceinline__ void split2(float a, float b, uint32_t& hi, uint32_t& lo) {
    __nv_bfloat16 ha = __float2bfloat16(a), hb = __float2bfloat16(b);
    float ra = a - __bfloat162float(ha), rb = b - __bfloat162float(hb);
    __nv_bfloat16 la = __float2bfloat16(ra), lb = __float2bfloat16(rb);
    hi = (uint32_t)__bfloat16_as_ushort(ha) | ((uint32_t)__bfloat16_as_ushort(hb) << 16);
    lo = (uint32_t)__bfloat16_as_ushort(la) | ((uint32_t)__bfloat16_as_ushort(lb) << 16);
}
__device__ __forceinline__ uint32_t hi2(uint2 v) { return (v.x >> 16) | (v.y & 0xffff0000u); }
__device__ __forceinline__ uint32_t lo2(uint2 v) { return (v.x & 0xffffu) | (v.y << 16); }

__device__ __forceinline__ void mma16816(float (&c)[4], const uint32_t (&a)[4],
                                         uint32_t b0, uint32_t b1) {
    asm volatile(
        "mma.sync.aligned.m16n8k16.row.col.f32.bf16.bf16.f32 "
        "{%0,%1,%2,%3},{%4,%5,%6,%7},{%8,%9},{%0,%1,%2,%3};"
        : "+f"(c[0]), "+f"(c[1]), "+f"(c[2]), "+f"(c[3])
        : "r"(a[0]), "r"(a[1]), "r"(a[2]), "r"(a[3]), "r"(b0), "r"(b1));
}

// ============================================================================
// k_prep: weights -> mma fragment order (hi/lo split), BN fold
// ============================================================================
__global__ void __launch_bounds__(256) k_prep(
    const float* __restrict__ w1, const float* __restrict__ w2,
    const float* __restrict__ wf,
    const float* __restrict__ gamma, const float* __restrict__ beta,
    const float* __restrict__ mean,  const float* __restrict__ var)
{
    int i = blockIdx.x * 256 + threadIdx.x;
    if (i < 64) {
        float s = gamma[i] * rsqrtf(var[i] + 1e-5f);
        g_bns[i] = s;
        g_bnb[i] = beta[i] - mean[i] * s;
    }
    if (i < 2 * 16 * 8 * 32 * 2) {           // 1x1 weights
        int j    = i & 1;
        int lane = (i >> 1) & 31;
        int nf   = (i >> 6) & 7;
        int ks   = (i >> 9) & 15;
        int wh   = i >> 13;
        int n   = nf * 8 + (lane >> 2);
        int ch0 = ks * 16 + (lane & 3) * 2 + j * 8;
        const float* w = wh ? w2 : w1;
        float w0 = w[n * CIN + ch0], w1v = w[n * CIN + ch0 + 1];
        uint32_t hi, lo; split2(w0, w1v, hi, lo);
        int base = (((wh * 16 + ks) * 8 + nf) * 32 + lane) * 4;
        g_wd[base + j] = hi;
        g_wd[base + 2 + j] = lo;
    }
    int m = i - 2 * 16 * 8 * 32 * 2;
    if (m >= 0 && m < 9 * 8 * 8 * 32 * 2) {  // 3x3 weights
        int j    = m & 1;
        int lane = (m >> 1) & 31;
        int nf   = (m >> 6) & 7;
        int ks   = (m >> 9) & 7;
        int tap  = m >> 12;
        int n   = nf * 8 + (lane >> 2);
        int ch0 = ks * 16 + (lane & 3) * 2 + j * 8;
        float w0 = wf[n * (128 * 9) + ch0 * 9 + tap];
        float w1v = wf[n * (128 * 9) + (ch0 + 1) * 9 + tap];
        uint32_t hi, lo; split2(w0, w1v, hi, lo);
        int base = (((tap * 8 + ks) * 8 + nf) * 32 + lane) * 4;
        g_wf[base + j] = hi;
        g_wf[base + 2 + j] = lo;
    }
}

// ============================================================================
// k1: both 1x1 convs via mma.sync bf16 3-pass. CTA = 256 px x 64 out-ch;
// warp = 32 px (two 16-px m-tiles sharing B fragments).
// ============================================================================
__global__ void __launch_bounds__(256) k1_mma(
    const float* __restrict__ x1, const float* __restrict__ x2)
{
    extern __shared__ uint4 sB[];            // 4096 uint4 = 64KB
    const int tid = threadIdx.x, lane = tid & 31, wm = tid >> 5;
    const int pt = blockIdx.x, nb = blockIdx.y, wh = blockIdx.z;
    const int kq = lane & 3, nr = lane >> 2;

    const uint4* wd4 = (const uint4*)g_wd + wh * 4096;
#pragma unroll
    for (int it = 0; it < 16; it++) sB[tid + it * 256] = wd4[tid + it * 256];
    __syncthreads();

    const float* X = (wh ? x2 : x1) + (size_t)nb * CIN * HW;
    const int base = pt * 256 + wm * 32 + nr;   // px for group 0

    float acc[2][8][4];
#pragma unroll
    for (int t = 0; t < 2; t++)
#pragma unroll
        for (int f = 0; f < 8; f++)
#pragma unroll
            for (int q = 0; q < 4; q++) acc[t][f][q] = 0.f;

    for (int ks = 0; ks < 16; ks++) {
        const float* Xc = X + (size_t)(ks * 16 + 2 * kq) * HW;
        uint32_t Ahi[2][4], Alo[2][4];
#pragma unroll
        for (int t = 0; t < 2; t++) {
            const int p0 = base + t * 16, p1 = p0 + 8;
            float f00 = Xc[p0],          f01 = Xc[HW + p0];
            float f08 = Xc[8 * HW + p0], f09 = Xc[9 * HW + p0];
            float f10 = Xc[p1],          f11 = Xc[HW + p1];
            float f18 = Xc[8 * HW + p1], f19 = Xc[9 * HW + p1];
            split2(f00, f01, Ahi[t][0], Alo[t][0]);
            split2(f10, f11, Ahi[t][1], Alo[t][1]);
            split2(f08, f09, Ahi[t][2], Alo[t][2]);
            split2(f18, f19, Ahi[t][3], Alo[t][3]);
        }
#pragma unroll
        for (int nf = 0; nf < 8; nf++) {
            uint4 b = sB[(ks * 8 + nf) * 32 + lane];
            mma16816(acc[0][nf], Ahi[0], b.x, b.y);
            mma16816(acc[0][nf], Ahi[0], b.z, b.w);
            mma16816(acc[0][nf], Alo[0], b.x, b.y);
            mma16816(acc[1][nf], Ahi[1], b.x, b.y);
            mma16816(acc[1][nf], Ahi[1], b.z, b.w);
            mma16816(acc[1][nf], Alo[1], b.x, b.y);
        }
    }

    // epilogue: pack to g_y [chunk][pix][8]
    uint32_t* gy = g_y + (size_t)nb * 16 * HW * 8;
#pragma unroll
    for (int t = 0; t < 2; t++) {
#pragma unroll
        for (int nf = 0; nf < 8; nf++) {
            const int chunk = wh * 8 + nf;
            const int pA = base + t * 16, pB = pA + 8;
            *(uint2*)&gy[((size_t)chunk * HW + pA) * 8 + 2 * kq] =
                make_uint2(split_pack(acc[t][nf][0]), split_pack(acc[t][nf][1]));
            *(uint2*)&gy[((size_t)chunk * HW + pB) * 8 + 2 * kq] =
                make_uint2(split_pack(acc[t][nf][2]), split_pack(acc[t][nf][3]));
        }
    }
}

// ============================================================================
// k2: conv3x3 (128->64) + BN + ReLU via mma.sync bf16 3-pass.
// CTA = one full image row (256 px) x 64 ch; warp = 32 px (2 m-tiles).
// 9 taps = pixel-shifted accumulating GEMMs; B double-buffered via cp.async.
// ============================================================================
__global__ void __launch_bounds__(256) k2_mma()
{
    extern __shared__ uint4 sB2[];           // 2 x 2048 uint4 = 64KB
    const int tid = threadIdx.x, lane = tid & 31, wm = tid >> 5;
    const int y = blockIdx.x, nb = blockIdx.y;
    const int kq = lane & 3, nr = lane >> 2;
    const uint32_t smb = smem_u32(sB2);

    float acc[2][8][4];
#pragma unroll
    for (int t = 0; t < 2; t++)
#pragma unroll
        for (int f = 0; f < 8; f++)
#pragma unroll
            for (int q = 0; q < 4; q++) acc[t][f][q] = 0.f;

    const uint2* Au = (const uint2*)(g_y + (size_t)nb * 16 * HW * 8);
    const uint4* wf4 = (const uint4*)g_wf;

    // stage tap 0
#pragma unroll
    for (int it = 0; it < 8; it++)
        cp_async16(smb + (tid + it * 256) * 16, &wf4[tid + it * 256]);
    cp_commit(); cp_wait0();
    __syncthreads();

    for (int tap = 0; tap < 9; tap++) {
        if (tap < 8) {
#pragma unroll
            for (int it = 0; it < 8; it++)
                cp_async16(smb + ((tap + 1) & 1) * 32768 + (tid + it * 256) * 16,
                           &wf4[(tap + 1) * 2048 + tid + it * 256]);
            cp_commit();
        }
        const int dy = tap / 3 - 1, dx = tap % 3 - 1;
        const int gyr = y + dy;
        const bool okY = (unsigned)gyr < (unsigned)Hh;
        int  gp[4]; bool vg[4];
#pragma unroll
        for (int g = 0; g < 4; g++) {
            int gx = wm * 32 + g * 8 + nr + dx;
            vg[g] = okY && (unsigned)gx < (unsigned)Ww;
            gp[g] = gyr * Ww + gx;
        }
        const uint4* sbuf = sB2 + (tap & 1) * 2048;

#pragma unroll 2
        for (int ks = 0; ks < 8; ks++) {
            const size_t cA = (size_t)(2 * ks) * HW, cB = cA + HW;
            uint2 q[4][2];
#pragma unroll
            for (int g = 0; g < 4; g++) {
                q[g][0] = vg[g] ? Au[(cA + gp[g]) * 4 + kq] : make_uint2(0u, 0u);
                q[g][1] = vg[g] ? Au[(cB + gp[g]) * 4 + kq] : make_uint2(0u, 0u);
            }
            uint32_t Ahi[2][4], Alo[2][4];
#pragma unroll
            for (int t = 0; t < 2; t++) {
                Ahi[t][0] = hi2(q[2 * t][0]);     Alo[t][0] = lo2(q[2 * t][0]);
                Ahi[t][1] = hi2(q[2 * t + 1][0]); Alo[t][1] = lo2(q[2 * t + 1][0]);
                Ahi[t][2] = hi2(q[2 * t][1]);     Alo[t][2] = lo2(q[2 * t][1]);
                Ahi[t][3] = hi2(q[2 * t + 1][1]); Alo[t][3] = lo2(q[2 * t + 1][1]);
            }
#pragma unroll
            for (int nf = 0; nf < 8; nf++) {
                uint4 b = sbuf[(ks * 8 + nf) * 32 + lane];
                mma16816(acc[0][nf], Ahi[0], b.x, b.y);
                mma16816(acc[0][nf], Ahi[0], b.z, b.w);
                mma16816(acc[0][nf], Alo[0], b.x, b.y);
                mma16816(acc[1][nf], Ahi[1], b.x, b.y);
                mma16816(acc[1][nf], Ahi[1], b.z, b.w);
                mma16816(acc[1][nf], Alo[1], b.x, b.y);
            }
        }
        cp_wait0();
        __syncthreads();
    }

    // epilogue: BN + ReLU -> g_x channel-major
    float* Xo = g_x + (size_t)nb * Tc * HW;
#pragma unroll
    for (int t = 0; t < 2; t++) {
        const int op0 = y * Ww + wm * 32 + t * 16 + nr;
        const int op1 = op0 + 8;
#pragma unroll
        for (int nf = 0; nf < 8; nf++) {
            int ch = nf * 8 + 2 * kq;
            float s0 = g_bns[ch], b0 = g_bnb[ch];
            float s1 = g_bns[ch + 1], b1 = g_bnb[ch + 1];
            float r00 = acc[t][nf][0] * s0 + b0; r00 = r00 > 0.f ? r00 : 0.f;
            float r01 = acc[t][nf][1] * s1 + b1; r01 = r01 > 0.f ? r01 : 0.f;
            float r10 = acc[t][nf][2] * s0 + b0; r10 = r10 > 0.f ? r10 : 0.f;
            float r11 = acc[t][nf][3] * s1 + b1; r11 = r11 > 0.f ? r11 : 0.f;
            Xo[(size_t)ch * HW + op0]       = r00;
            Xo[(size_t)(ch + 1) * HW + op0] = r01;
            Xo[(size_t)ch * HW + op1]       = r10;
            Xo[(size_t)(ch + 1) * HW + op1] = r11;
        }
    }
}

// ============================================================================
// k3: conv3x3 (64 -> 2, pad 1) -> flow, channel-split x2 (partials summed in k4)
// ============================================================================
__global__ void __launch_bounds__(256) k_flowconv(const float* __restrict__ w2)
{
    __shared__ __align__(16) float Xs[8 * 10 * 36];
    __shared__ __align__(16) float Ws[2 * 32 * 9];

    const int bx = blockIdx.x, by = blockIdx.y;
    const int nb = blockIdx.z >> 1, h = blockIdx.z & 1;
    const int tid = threadIdx.x;
    const int py = tid >> 5, px = tid & 31;

    for (int i = tid; i < 2 * 32 * 9; i += 256) {
        int oc = i / 288, c = (i / 9) % 32, tap = i % 9;
        Ws[i] = w2[oc * 576 + (h * 32 + c) * 9 + tap];
    }

    float a0 = 0.f, a1 = 0.f;
    const float* Xb = g_x + ((size_t)nb * Tc + h * 32) * HW;

    for (int c0 = 0; c0 < 32; c0 += 8) {
        for (int i = tid; i < 8 * 10 * 34; i += 256) {
            int cc = i / 340;
            int rem = i - cc * 340;
            int ry = rem / 34, rx = rem - (rem / 34) * 34;
            int gy = by * 8 + ry - 1;
            int gx = bx * 32 + rx - 1;
            float v = 0.f;
            if ((unsigned)gy < (unsigned)Hh && (unsigned)gx < (unsigned)Ww)
                v = Xb[(size_t)(c0 + cc) * HW + gy * Ww + gx];
            Xs[cc * 360 + ry * 36 + rx] = v;
        }
        __syncthreads();
#pragma unroll
        for (int cc = 0; cc < 8; cc++) {
            int c = c0 + cc;
#pragma unroll
            for (int dy = 0; dy < 3; dy++) {
#pragma unroll
                for (int dx = 0; dx < 3; dx++) {
                    float xv = Xs[cc * 360 + (py + dy) * 36 + (px + dx)];
                    int tap = dy * 3 + dx;
                    a0 += Ws[c * 9 + tap] * xv;
                    a1 += Ws[288 + c * 9 + tap] * xv;
                }
            }
        }
        __syncthreads();
    }

    const int oy = by * 8 + py, ox = bx * 32 + px;
    g_flow[h][((size_t)(nb * 2 + 0) * Hh + oy) * Ww + ox] = a0;
    g_flow[h][((size_t)(nb * 2 + 1) * Hh + oy) * Ww + ox] = a1;
}

// ============================================================================
// k4: flow_warp (torch repeat(c,1,1,1) batch-aliasing); sums partial flows
// ============================================================================
__global__ void __launch_bounds__(256) k_warp(
    const float* __restrict__ pred, float* __restrict__ out)
{
    const int idx = blockIdx.x * 256 + threadIdx.x;
    const int x = idx & (Ww - 1);
    const int y = (idx >> 8) & (Hh - 1);
    const int t = idx >> 15;
    const int fb = t & 3;

    const size_t fx_i = ((size_t)(fb * 2 + 0) * Hh + y) * Ww + x;
    const size_t fy_i = ((size_t)(fb * 2 + 1) * Hh + y) * Ww + x;
    const float fx = g_flow[0][fx_i] + g_flow[1][fx_i];
    const float fy = g_flow[0][fy_i] + g_flow[1][fy_i];

    const float gx = -1.f + 2.f * (float)x / (float)(Ww - 1);
    const float gy = -1.f + 2.f * (float)y / (float)(Hh - 1);
    const float sx = gx + fx / (float)Ww;
    const float sy = gy + fy / (float)Hh;
    const float ix = ((sx + 1.f) * (float)Ww - 1.f) * 0.5f;
    const float iy = ((sy + 1.f) * (float)Hh - 1.f) * 0.5f;

    const float x0f = floorf(ix), y0f = floorf(iy);
    const float wx = ix - x0f, wy = iy - y0f;
    const int x0 = (int)x0f, y0 = (int)y0f;

    const float* img = pred + (size_t)t * HW;
    auto samp = [&](int yy, int xx) -> float {
        return (xx >= 0 && xx < Ww && yy >= 0 && yy < Hh) ? img[yy * Ww + xx] : 0.f;
    };
    const float v00 = samp(y0, x0);
    const float v01 = samp(y0, x0 + 1);
    const float v10 = samp(y0 + 1, x0);
    const float v11 = samp(y0 + 1, x0 + 1);

    const float top = v00 * (1.f - wx) + v01 * wx;
    const float bot = v10 * (1.f - wx) + v11 * wx;
    out[idx] = top * (1.f - wy) + bot * wy;
}

// ============================================================================
// launch
// ============================================================================
extern "C" void kernel_launch(void* const* d_in, const int* in_sizes, int n_in,
                              void* d_out, int out_size)
{
    const float* t1_feature = (const float*)d_in[0];
    const float* t2_feature = (const float*)d_in[1];
    const float* t2_pred    = (const float*)d_in[2];
    const float* w_down1    = (const float*)d_in[3];
    const float* w_down2    = (const float*)d_in[4];
    const float* w_flow1    = (const float*)d_in[5];
    const float* bn_gamma   = (const float*)d_in[6];
    const float* bn_beta    = (const float*)d_in[7];
    const float* bn_mean    = (const float*)d_in[8];
    const float* bn_var     = (const float*)d_in[9];
    const float* w_flow2    = (const float*)d_in[10];
    float* out = (float*)d_out;

    cudaFuncSetAttribute(k1_mma, cudaFuncAttributeMaxDynamicSharedMemorySize, 65536);
    cudaFuncSetAttribute(k2_mma, cudaFuncAttributeMaxDynamicSharedMemorySize, 65536);

    k_prep<<<(2 * 16 * 8 * 32 * 2 + 9 * 8 * 8 * 32 * 2 + 255) / 256, 256>>>(
        w_down1, w_down2, w_flow1, bn_gamma, bn_beta, bn_mean, bn_var);
    k1_mma<<<dim3(128, NB, 2), 256, 65536>>>(t1_feature, t2_feature);
    k2_mma<<<dim3(Hh, NB), 256, 65536>>>();
    k_flowconv<<<dim3(Ww / 32, Hh / 8, NB * 2), 256>>>(w_flow2);
    k_warp<<<(NB * CCLS * HW) / 256, 256>>>(t2_pred, out);
}

// round 7
// speedup vs baseline: 1.3327x; 1.3327x over previous
#include <cuda_runtime.h>
#include <cuda_fp16.h>
#include <cstdint>

#define Hh 128
#define Ww 256
#define HW (Hh*Ww)
#define NB 4
#define CIN 256
#define Tc 64
#define CCLS 19

// ---------------- scratch (allocation-free: __device__ globals) ----------------
// g_y: [nb][chunk16][pix][8 u32]; u32 = fp16 hi (upper) | fp16 lo (lower) per channel
__device__ __align__(16) uint32_t g_y[NB * 16 * HW * 8];
__device__ float    g_x[NB * Tc * HW];        // after BN+ReLU (k3 input)
__device__ float    g_flow[2][NB * 2 * HW];   // partial flows (channel-split halves)
// B fragments (hi only, 2-pass): [..][lane][2] u32 = {hi_reg0, hi_reg1}
__device__ __align__(16) uint32_t g_wd[2 * 16 * 8 * 32 * 2];   // 1x1: [wh][ks16][nf8][lane][2]
__device__ __align__(16) uint32_t g_wf[9 * 8 * 8 * 32 * 2];    // 3x3: [tap][ks8][nf8][lane][2]
__device__ float    g_bns[64], g_bnb[64];

// ---------------- helpers ----------------
__device__ __forceinline__ uint32_t smem_u32(const void* p) {
    uint32_t a;
    asm("{ .reg .u64 t; cvta.to.shared.u64 t, %1; cvt.u32.u64 %0, t; }" : "=r"(a) : "l"(p));
    return a;
}
__device__ __forceinline__ void cp_async16(uint32_t saddr, const void* g) {
    asm volatile("cp.async.cg.shared.global [%0], [%1], 16;" :: "r"(saddr), "l"(g));
}
__device__ __forceinline__ void cp_commit() { asm volatile("cp.async.commit_group;"); }
__device__ __forceinline__ void cp_wait0()  { asm volatile("cp.async.wait_group 0;"); }

// fp16 hi/lo split, packed hi|lo into one u32
__device__ __forceinline__ uint32_t split_pack_h(float v) {
    __half h = __float2half_rn(v);
    __half l = __float2half_rn(v - __half2float(h));
    return ((uint32_t)__half_as_ushort(h) << 16) | (uint32_t)__half_as_ushort(l);
}
// two floats -> fp16x2 hi-reg and lo-reg (element0 in lower half)
__device__ __forceinline__ void split2h(float a, float b, uint32_t& hi, uint32_t& lo) {
    __half ha = __float2half_rn(a), hb = __float2half_rn(b);
    __half la = __float2half_rn(a - __half2float(ha));
    __half lb = __float2half_rn(b - __half2float(hb));
    hi = (uint32_t)__half_as_ushort(ha) | ((uint32_t)__half_as_ushort(hb) << 16);
    lo = (uint32_t)__half_as_ushort(la) | ((uint32_t)__half_as_ushort(lb) << 16);
}
__device__ __forceinline__ uint32_t hi2(uint2 v) { return (v.x >> 16) | (v.y & 0xffff0000u); }
__device__ __forceinline__ uint32_t lo2(uint2 v) { return (v.x & 0xffffu) | (v.y << 16); }

__device__ __forceinline__ void mma16816h(float (&c)[4], const uint32_t (&a)[4],
                                          uint32_t b0, uint32_t b1) {
    asm volatile(
        "mma.sync.aligned.m16n8k16.row.col.f32.f16.f16.f32 "
        "{%0,%1,%2,%3},{%4,%5,%6,%7},{%8,%9},{%0,%1,%2,%3};"
        : "+f"(c[0]), "+f"(c[1]), "+f"(c[2]), "+f"(c[3])
        : "r"(a[0]), "r"(a[1]), "r"(a[2]), "r"(a[3]), "r"(b0), "r"(b1));
}

// ============================================================================
// k_prep: weights -> fp16 hi fragments, BN fold
// ============================================================================
__global__ void __launch_bounds__(256) k_prep(
    const float* __restrict__ w1, const float* __restrict__ w2,
    const float* __restrict__ wf,
    const float* __restrict__ gamma, const float* __restrict__ beta,
    const float* __restrict__ mean,  const float* __restrict__ var)
{
    int i = blockIdx.x * 256 + threadIdx.x;
    if (i < 64) {
        float s = gamma[i] * rsqrtf(var[i] + 1e-5f);
        g_bns[i] = s;
        g_bnb[i] = beta[i] - mean[i] * s;
    }
    if (i < 2 * 16 * 8 * 32 * 2) {           // 1x1 weights (16384)
        int j    = i & 1;
        int lane = (i >> 1) & 31;
        int nf   = (i >> 6) & 7;
        int ks   = (i >> 9) & 15;
        int wh   = i >> 13;
        int n   = nf * 8 + (lane >> 2);
        int ch0 = ks * 16 + (lane & 3) * 2 + j * 8;
        const float* w = wh ? w2 : w1;
        __half h0 = __float2half_rn(w[n * CIN + ch0]);
        __half h1 = __float2half_rn(w[n * CIN + ch0 + 1]);
        g_wd[(((wh * 16 + ks) * 8 + nf) * 32 + lane) * 2 + j] =
            (uint32_t)__half_as_ushort(h0) | ((uint32_t)__half_as_ushort(h1) << 16);
    }
    int m = i - 2 * 16 * 8 * 32 * 2;
    if (m >= 0 && m < 9 * 8 * 8 * 32 * 2) {  // 3x3 weights (36864)
        int j    = m & 1;
        int lane = (m >> 1) & 31;
        int nf   = (m >> 6) & 7;
        int ks   = (m >> 9) & 7;
        int tap  = m >> 12;
        int n   = nf * 8 + (lane >> 2);
        int ch0 = ks * 16 + (lane & 3) * 2 + j * 8;
        __half h0 = __float2half_rn(wf[n * (128 * 9) + ch0 * 9 + tap]);
        __half h1 = __float2half_rn(wf[n * (128 * 9) + (ch0 + 1) * 9 + tap]);
        g_wf[(((tap * 8 + ks) * 8 + nf) * 32 + lane) * 2 + j] =
            (uint32_t)__half_as_ushort(h0) | ((uint32_t)__half_as_ushort(h1) << 16);
    }
}

// profiler-steering no-op
__global__ void k_probe() {}

// ============================================================================
// k1: both 1x1 convs, fp16 2-pass mma. CTA = 256 px x 64 out-ch;
// warp = 32 px (two 16-px m-tiles sharing B). A prefetched one k-step ahead.
// ============================================================================
__global__ void __launch_bounds__(256) k1_mma(
    const float* __restrict__ x1, const float* __restrict__ x2)
{
    __shared__ uint2 sB[16 * 8 * 32];        // 32KB
    const int tid = threadIdx.x, lane = tid & 31, wm = tid >> 5;
    const int pt = blockIdx.x, nb = blockIdx.y, wh = blockIdx.z;
    const int kq = lane & 3, nr = lane >> 2;

    const uint4* wd4 = (const uint4*)(g_wd + wh * 8192);
    uint4* sB4 = (uint4*)sB;
#pragma unroll
    for (int it = 0; it < 8; it++) sB4[tid + it * 256] = wd4[tid + it * 256];
    __syncthreads();

    const float* X = (wh ? x2 : x1) + (size_t)nb * CIN * HW;
    const int base = pt * 256 + wm * 32 + nr;

    float acc[2][8][4];
#pragma unroll
    for (int t = 0; t < 2; t++)
#pragma unroll
        for (int f = 0; f < 8; f++)
#pragma unroll
            for (int q = 0; q < 4; q++) acc[t][f][q] = 0.f;

    float fc[2][8], fn[2][8];
    auto loadA = [&](int ks, float (&fv)[2][8]) {
        const float* Xc = X + (size_t)(ks * 16 + 2 * kq) * HW;
#pragma unroll
        for (int t = 0; t < 2; t++) {
            const int p0 = base + t * 16, p1 = p0 + 8;
            fv[t][0] = Xc[p0];          fv[t][1] = Xc[HW + p0];
            fv[t][2] = Xc[8 * HW + p0]; fv[t][3] = Xc[9 * HW + p0];
            fv[t][4] = Xc[p1];          fv[t][5] = Xc[HW + p1];
            fv[t][6] = Xc[8 * HW + p1]; fv[t][7] = Xc[9 * HW + p1];
        }
    };
    loadA(0, fc);

#pragma unroll
    for (int ks = 0; ks < 16; ks++) {
        if (ks < 15) loadA(ks + 1, fn);
        uint32_t Ahi[2][4], Alo[2][4];
#pragma unroll
        for (int t = 0; t < 2; t++) {
            split2h(fc[t][0], fc[t][1], Ahi[t][0], Alo[t][0]);
            split2h(fc[t][4], fc[t][5], Ahi[t][1], Alo[t][1]);
            split2h(fc[t][2], fc[t][3], Ahi[t][2], Alo[t][2]);
            split2h(fc[t][6], fc[t][7], Ahi[t][3], Alo[t][3]);
        }
#pragma unroll
        for (int nf = 0; nf < 8; nf++) {
            uint2 b = sB[(ks * 8 + nf) * 32 + lane];
            mma16816h(acc[0][nf], Ahi[0], b.x, b.y);
            mma16816h(acc[0][nf], Alo[0], b.x, b.y);
            mma16816h(acc[1][nf], Ahi[1], b.x, b.y);
            mma16816h(acc[1][nf], Alo[1], b.x, b.y);
        }
#pragma unroll
        for (int t = 0; t < 2; t++)
#pragma unroll
            for (int e = 0; e < 8; e++) fc[t][e] = fn[t][e];
    }

    // epilogue: pack to g_y [chunk][pix][8]
    uint32_t* gy = g_y + (size_t)nb * 16 * HW * 8;
#pragma unroll
    for (int t = 0; t < 2; t++) {
#pragma unroll
        for (int nf = 0; nf < 8; nf++) {
            const int chunk = wh * 8 + nf;
            const int pA = base + t * 16, pB = pA + 8;
            *(uint2*)&gy[((size_t)chunk * HW + pA) * 8 + 2 * kq] =
                make_uint2(split_pack_h(acc[t][nf][0]), split_pack_h(acc[t][nf][1]));
            *(uint2*)&gy[((size_t)chunk * HW + pB) * 8 + 2 * kq] =
                make_uint2(split_pack_h(acc[t][nf][2]), split_pack_h(acc[t][nf][3]));
        }
    }
}

// ============================================================================
// k2: conv3x3 (128->64) + BN + ReLU, fp16 2-pass mma.
// CTA = one image row (256 px) x 64 ch; 9 taps = pixel-shifted accumulating
// GEMMs. B double-buffered via cp.async; A prefetched one k-step ahead.
// ============================================================================
__global__ void __launch_bounds__(256) k2_mma()
{
    __shared__ uint2 sB2[2][2048];           // 2 x 16KB
    const int tid = threadIdx.x, lane = tid & 31, wm = tid >> 5;
    const int y = blockIdx.x, nb = blockIdx.y;
    const int kq = lane & 3, nr = lane >> 2;
    const uint32_t smb = smem_u32(sB2);

    float acc[2][8][4];
#pragma unroll
    for (int t = 0; t < 2; t++)
#pragma unroll
        for (int f = 0; f < 8; f++)
#pragma unroll
            for (int q = 0; q < 4; q++) acc[t][f][q] = 0.f;

    const uint2* Au = (const uint2*)(g_y + (size_t)nb * 16 * HW * 8);
    const uint4* wf4 = (const uint4*)g_wf;   // 1024 uint4 per tap

    // stage tap 0
#pragma unroll
    for (int it = 0; it < 4; it++)
        cp_async16(smb + (tid + it * 256) * 16, &wf4[tid + it * 256]);
    cp_commit(); cp_wait0();
    __syncthreads();

    for (int tap = 0; tap < 9; tap++) {
        if (tap < 8) {
#pragma unroll
            for (int it = 0; it < 4; it++)
                cp_async16(smb + ((tap + 1) & 1) * 16384 + (tid + it * 256) * 16,
                           &wf4[(tap + 1) * 1024 + tid + it * 256]);
            cp_commit();
        }
        const int dy = tap / 3 - 1, dx = tap % 3 - 1;
        const int gyr = y + dy;
        const bool okY = (unsigned)gyr < (unsigned)Hh;
        int gp[4]; bool vg[4];
#pragma unroll
        for (int g = 0; g < 4; g++) {
            int gx = wm * 32 + g * 8 + nr + dx;
            vg[g] = okY && (unsigned)gx < (unsigned)Ww;
            gp[g] = gyr * Ww + gx;
        }
        const uint2* sbuf = sB2[tap & 1];

        uint2 qc[4][2], qn[4][2];
        auto loadA = [&](int ks, uint2 (&qv)[4][2]) {
            const size_t cA = (size_t)(2 * ks) * HW, cB = cA + HW;
#pragma unroll
            for (int g = 0; g < 4; g++) {
                qv[g][0] = vg[g] ? Au[(cA + gp[g]) * 4 + kq] : make_uint2(0u, 0u);
                qv[g][1] = vg[g] ? Au[(cB + gp[g]) * 4 + kq] : make_uint2(0u, 0u);
            }
        };
        loadA(0, qc);

#pragma unroll
        for (int ks = 0; ks < 8; ks++) {
            if (ks < 7) loadA(ks + 1, qn);
            uint32_t Ahi[2][4], Alo[2][4];
#pragma unroll
            for (int t = 0; t < 2; t++) {
                Ahi[t][0] = hi2(qc[2 * t][0]);     Alo[t][0] = lo2(qc[2 * t][0]);
                Ahi[t][1] = hi2(qc[2 * t + 1][0]); Alo[t][1] = lo2(qc[2 * t + 1][0]);
                Ahi[t][2] = hi2(qc[2 * t][1]);     Alo[t][2] = lo2(qc[2 * t][1]);
                Ahi[t][3] = hi2(qc[2 * t + 1][1]); Alo[t][3] = lo2(qc[2 * t + 1][1]);
            }
#pragma unroll
            for (int nf = 0; nf < 8; nf++) {
                uint2 b = sbuf[(ks * 8 + nf) * 32 + lane];
                mma16816h(acc[0][nf], Ahi[0], b.x, b.y);
                mma16816h(acc[0][nf], Alo[0], b.x, b.y);
                mma16816h(acc[1][nf], Ahi[1], b.x, b.y);
                mma16816h(acc[1][nf], Alo[1], b.x, b.y);
            }
#pragma unroll
            for (int g = 0; g < 4; g++) {
                qc[g][0] = qn[g][0]; qc[g][1] = qn[g][1];
            }
        }
        cp_wait0();
        __syncthreads();
    }

    // epilogue: BN + ReLU -> g_x channel-major
    float* Xo = g_x + (size_t)nb * Tc * HW;
#pragma unroll
    for (int t = 0; t < 2; t++) {
        const int op0 = y * Ww + wm * 32 + t * 16 + nr;
        const int op1 = op0 + 8;
#pragma unroll
        for (int nf = 0; nf < 8; nf++) {
            int ch = nf * 8 + 2 * kq;
            float s0 = g_bns[ch], b0 = g_bnb[ch];
            float s1 = g_bns[ch + 1], b1 = g_bnb[ch + 1];
            float r00 = acc[t][nf][0] * s0 + b0; r00 = r00 > 0.f ? r00 : 0.f;
            float r01 = acc[t][nf][1] * s1 + b1; r01 = r01 > 0.f ? r01 : 0.f;
            float r10 = acc[t][nf][2] * s0 + b0; r10 = r10 > 0.f ? r10 : 0.f;
            float r11 = acc[t][nf][3] * s1 + b1; r11 = r11 > 0.f ? r11 : 0.f;
            Xo[(size_t)ch * HW + op0]       = r00;
            Xo[(size_t)(ch + 1) * HW + op0] = r01;
            Xo[(size_t)ch * HW + op1]       = r10;
            Xo[(size_t)(ch + 1) * HW + op1] = r11;
        }
    }
}

// ============================================================================
// k3: conv3x3 (64 -> 2, pad 1) -> flow, channel-split x2 (summed in k4)
// ============================================================================
__global__ void __launch_bounds__(256) k_flowconv(const float* __restrict__ w2)
{
    __shared__ __align__(16) float Xs[8 * 10 * 36];
    __shared__ __align__(16) float Ws[2 * 32 * 9];

    const int bx = blockIdx.x, by = blockIdx.y;
    const int nb = blockIdx.z >> 1, h = blockIdx.z & 1;
    const int tid = threadIdx.x;
    const int py = tid >> 5, px = tid & 31;

    for (int i = tid; i < 2 * 32 * 9; i += 256) {
        int oc = i / 288, c = (i / 9) % 32, tap = i % 9;
        Ws[i] = w2[oc * 576 + (h * 32 + c) * 9 + tap];
    }

    float a0 = 0.f, a1 = 0.f;
    const float* Xb = g_x + ((size_t)nb * Tc + h * 32) * HW;

    for (int c0 = 0; c0 < 32; c0 += 8) {
        for (int i = tid; i < 8 * 10 * 34; i += 256) {
            int cc = i / 340;
            int rem = i - cc * 340;
            int ry = rem / 34, rx = rem - (rem / 34) * 34;
            int gy = by * 8 + ry - 1;
            int gx = bx * 32 + rx - 1;
            float v = 0.f;
            if ((unsigned)gy < (unsigned)Hh && (unsigned)gx < (unsigned)Ww)
                v = Xb[(size_t)(c0 + cc) * HW + gy * Ww + gx];
            Xs[cc * 360 + ry * 36 + rx] = v;
        }
        __syncthreads();
#pragma unroll
        for (int cc = 0; cc < 8; cc++) {
            int c = c0 + cc;
#pragma unroll
            for (int dy = 0; dy < 3; dy++) {
#pragma unroll
                for (int dx = 0; dx < 3; dx++) {
                    float xv = Xs[cc * 360 + (py + dy) * 36 + (px + dx)];
                    int tap = dy * 3 + dx;
                    a0 += Ws[c * 9 + tap] * xv;
                    a1 += Ws[288 + c * 9 + tap] * xv;
                }
            }
        }
        __syncthreads();
    }

    const int oy = by * 8 + py, ox = bx * 32 + px;
    g_flow[h][((size_t)(nb * 2 + 0) * Hh + oy) * Ww + ox] = a0;
    g_flow[h][((size_t)(nb * 2 + 1) * Hh + oy) * Ww + ox] = a1;
}

// ============================================================================
// k4: flow_warp (torch repeat(c,1,1,1) batch-aliasing); sums partial flows
// ============================================================================
__global__ void __launch_bounds__(256) k_warp(
    const float* __restrict__ pred, float* __restrict__ out)
{
    const int idx = blockIdx.x * 256 + threadIdx.x;
    const int x = idx & (Ww - 1);
    const int y = (idx >> 8) & (Hh - 1);
    const int t = idx >> 15;
    const int fb = t & 3;

    const size_t fx_i = ((size_t)(fb * 2 + 0) * Hh + y) * Ww + x;
    const size_t fy_i = ((size_t)(fb * 2 + 1) * Hh + y) * Ww + x;
    const float fx = g_flow[0][fx_i] + g_flow[1][fx_i];
    const float fy = g_flow[0][fy_i] + g_flow[1][fy_i];

    const float gx = -1.f + 2.f * (float)x / (float)(Ww - 1);
    const float gy = -1.f + 2.f * (float)y / (float)(Hh - 1);
    const float sx = gx + fx / (float)Ww;
    const float sy = gy + fy / (float)Hh;
    const float ix = ((sx + 1.f) * (float)Ww - 1.f) * 0.5f;
    const float iy = ((sy + 1.f) * (float)Hh - 1.f) * 0.5f;

    const float x0f = floorf(ix), y0f = floorf(iy);
    const float wx = ix - x0f, wy = iy - y0f;
    const int x0 = (int)x0f, y0 = (int)y0f;

    const float* img = pred + (size_t)t * HW;
    auto samp = [&](int yy, int xx) -> float {
        return (xx >= 0 && xx < Ww && yy >= 0 && yy < Hh) ? img[yy * Ww + xx] : 0.f;
    };
    const float v00 = samp(y0, x0);
    const float v01 = samp(y0, x0 + 1);
    const float v10 = samp(y0 + 1, x0);
    const float v11 = samp(y0 + 1, x0 + 1);

    const float top = v00 * (1.f - wx) + v01 * wx;
    const float bot = v10 * (1.f - wx) + v11 * wx;
    out[idx] = top * (1.f - wy) + bot * wy;
}

// ============================================================================
// launch
// ============================================================================
extern "C" void kernel_launch(void* const* d_in, const int* in_sizes, int n_in,
                              void* d_out, int out_size)
{
    const float* t1_feature = (const float*)d_in[0];
    const float* t2_feature = (const float*)d_in[1];
    const float* t2_pred    = (const float*)d_in[2];
    const float* w_down1    = (const float*)d_in[3];
    const float* w_down2    = (const float*)d_in[4];
    const float* w_flow1    = (const float*)d_in[5];
    const float* bn_gamma   = (const float*)d_in[6];
    const float* bn_beta    = (const float*)d_in[7];
    const float* bn_mean    = (const float*)d_in[8];
    const float* bn_var     = (const float*)d_in[9];
    const float* w_flow2    = (const float*)d_in[10];
    float* out = (float*)d_out;

    k_prep<<<208, 256>>>(w_down1, w_down2, w_flow1, bn_gamma, bn_beta, bn_mean, bn_var);
    k1_mma<<<dim3(128, NB, 2), 256>>>(t1_feature, t2_feature);
    k_probe<<<1, 32>>>();
    k2_mma<<<dim3(Hh, NB), 256>>>();
    k_flowconv<<<dim3(Ww / 32, Hh / 8, NB * 2), 256>>>(w_flow2);
    k_warp<<<(NB * CCLS * HW) / 256, 256>>>(t2_pred, out);
}

// round 8
// speedup vs baseline: 1.5043x; 1.1288x over previous
#include <cuda_runtime.h>
#include <cuda_fp16.h>
#include <cstdint>

#define Hh 128
#define Ww 256
#define HW (Hh*Ww)
#define NB 4
#define CIN 256
#define Tc 64
#define CCLS 19

// ---------------- scratch (allocation-free: __device__ globals) ----------------
// g_y: [nb][chunk16][pix][8 u32]; u32 = fp16 hi (upper) | fp16 lo (lower) per channel
__device__ __align__(16) uint32_t g_y[NB * 16 * HW * 8];
__device__ float    g_x[NB * Tc * HW];        // after BN+ReLU (k3 input)
__device__ float    g_flow[2][NB * 2 * HW];   // partial flows (channel-split halves)
// B fragments (hi only, 2-pass): [..][lane][2] u32 = {hi_reg0, hi_reg1}
__device__ __align__(16) uint32_t g_wd[2 * 16 * 8 * 32 * 2];   // 1x1: [wh][ks16][nf8][lane][2]
__device__ __align__(16) uint32_t g_wf[9 * 8 * 8 * 32 * 2];    // 3x3: [tap][ks8][nf8][lane][2]
__device__ float    g_bns[64], g_bnb[64];

// ---------------- helpers ----------------
// fp16 hi/lo split, packed hi|lo into one u32
__device__ __forceinline__ uint32_t split_pack_h(float v) {
    __half h = __float2half_rn(v);
    __half l = __float2half_rn(v - __half2float(h));
    return ((uint32_t)__half_as_ushort(h) << 16) | (uint32_t)__half_as_ushort(l);
}
// two floats -> fp16x2 hi-reg and lo-reg (element0 in lower half)
__device__ __forceinline__ void split2h(float a, float b, uint32_t& hi, uint32_t& lo) {
    __half ha = __float2half_rn(a), hb = __float2half_rn(b);
    __half la = __float2half_rn(a - __half2float(ha));
    __half lb = __float2half_rn(b - __half2float(hb));
    hi = (uint32_t)__half_as_ushort(ha) | ((uint32_t)__half_as_ushort(hb) << 16);
    lo = (uint32_t)__half_as_ushort(la) | ((uint32_t)__half_as_ushort(lb) << 16);
}
__device__ __forceinline__ uint32_t hi2(uint2 v) { return (v.x >> 16) | (v.y & 0xffff0000u); }
__device__ __forceinline__ uint32_t lo2(uint2 v) { return (v.x & 0xffffu) | (v.y << 16); }

__device__ __forceinline__ void mma16816h(float (&c)[4], const uint32_t (&a)[4],
                                          uint32_t b0, uint32_t b1) {
    asm volatile(
        "mma.sync.aligned.m16n8k16.row.col.f32.f16.f16.f32 "
        "{%0,%1,%2,%3},{%4,%5,%6,%7},{%8,%9},{%0,%1,%2,%3};"
        : "+f"(c[0]), "+f"(c[1]), "+f"(c[2]), "+f"(c[3])
        : "r"(a[0]), "r"(a[1]), "r"(a[2]), "r"(a[3]), "r"(b0), "r"(b1));
}

// ============================================================================
// k_prep: weights -> fp16 hi fragments, BN fold
// ============================================================================
__global__ void __launch_bounds__(256) k_prep(
    const float* __restrict__ w1, const float* __restrict__ w2,
    const float* __restrict__ wf,
    const float* __restrict__ gamma, const float* __restrict__ beta,
    const float* __restrict__ mean,  const float* __restrict__ var)
{
    int i = blockIdx.x * 256 + threadIdx.x;
    if (i < 64) {
        float s = gamma[i] * rsqrtf(var[i] + 1e-5f);
        g_bns[i] = s;
        g_bnb[i] = beta[i] - mean[i] * s;
    }
    if (i < 2 * 16 * 8 * 32 * 2) {           // 1x1 weights (16384)
        int j    = i & 1;
        int lane = (i >> 1) & 31;
        int nf   = (i >> 6) & 7;
        int ks   = (i >> 9) & 15;
        int wh   = i >> 13;
        int n   = nf * 8 + (lane >> 2);
        int ch0 = ks * 16 + (lane & 3) * 2 + j * 8;
        const float* w = wh ? w2 : w1;
        __half h0 = __float2half_rn(w[n * CIN + ch0]);
        __half h1 = __float2half_rn(w[n * CIN + ch0 + 1]);
        g_wd[(((wh * 16 + ks) * 8 + nf) * 32 + lane) * 2 + j] =
            (uint32_t)__half_as_ushort(h0) | ((uint32_t)__half_as_ushort(h1) << 16);
    }
    int m = i - 2 * 16 * 8 * 32 * 2;
    if (m >= 0 && m < 9 * 8 * 8 * 32 * 2) {  // 3x3 weights (36864)
        int j    = m & 1;
        int lane = (m >> 1) & 31;
        int nf   = (m >> 6) & 7;
        int ks   = (m >> 9) & 7;
        int tap  = m >> 12;
        int n   = nf * 8 + (lane >> 2);
        int ch0 = ks * 16 + (lane & 3) * 2 + j * 8;
        __half h0 = __float2half_rn(wf[n * (128 * 9) + ch0 * 9 + tap]);
        __half h1 = __float2half_rn(wf[n * (128 * 9) + (ch0 + 1) * 9 + tap]);
        g_wf[(((tap * 8 + ks) * 8 + nf) * 32 + lane) * 2 + j] =
            (uint32_t)__half_as_ushort(h0) | ((uint32_t)__half_as_ushort(h1) << 16);
    }
}

// profiler-steering no-op (keeps ncu sampling k2_mma)
__global__ void k_probe() {}

// ============================================================================
// k1: both 1x1 convs, fp16 2-pass mma. CTA = 256 px x 64 out-ch;
// warp = 32 px. NO smem, NO barriers: B fragments LDG'd from L1-resident g_wd.
// ============================================================================
__global__ void __launch_bounds__(256, 2) k1_mma(
    const float* __restrict__ x1, const float* __restrict__ x2)
{
    const int tid = threadIdx.x, lane = tid & 31, wm = tid >> 5;
    const int pt = blockIdx.x, nb = blockIdx.y, wh = blockIdx.z;
    const int kq = lane & 3, nr = lane >> 2;

    const float* X = (wh ? x2 : x1) + (size_t)nb * CIN * HW;
    const uint2* Bw = (const uint2*)g_wd + ((size_t)wh * 16 * 8 * 32 + lane);
    const int base = pt * 256 + wm * 32 + nr;

    float acc[2][8][4];
#pragma unroll
    for (int t = 0; t < 2; t++)
#pragma unroll
        for (int f = 0; f < 8; f++)
#pragma unroll
            for (int q = 0; q < 4; q++) acc[t][f][q] = 0.f;

#pragma unroll 4
    for (int ks = 0; ks < 16; ks++) {
        const float* Xc = X + (size_t)(ks * 16 + 2 * kq) * HW;
        uint32_t Ahi[2][4], Alo[2][4];
#pragma unroll
        for (int t = 0; t < 2; t++) {
            const int p0 = base + t * 16, p1 = p0 + 8;
            float f0 = Xc[p0],          f1 = Xc[HW + p0];
            float f2 = Xc[8 * HW + p0], f3 = Xc[9 * HW + p0];
            float f4 = Xc[p1],          f5 = Xc[HW + p1];
            float f6 = Xc[8 * HW + p1], f7 = Xc[9 * HW + p1];
            split2h(f0, f1, Ahi[t][0], Alo[t][0]);
            split2h(f4, f5, Ahi[t][1], Alo[t][1]);
            split2h(f2, f3, Ahi[t][2], Alo[t][2]);
            split2h(f6, f7, Ahi[t][3], Alo[t][3]);
        }
#pragma unroll
        for (int nf = 0; nf < 8; nf++) {
            uint2 b = Bw[(ks * 8 + nf) * 32];
            mma16816h(acc[0][nf], Ahi[0], b.x, b.y);
            mma16816h(acc[0][nf], Alo[0], b.x, b.y);
            mma16816h(acc[1][nf], Ahi[1], b.x, b.y);
            mma16816h(acc[1][nf], Alo[1], b.x, b.y);
        }
    }

    // epilogue: pack to g_y [chunk][pix][8]
    uint32_t* gy = g_y + (size_t)nb * 16 * HW * 8;
#pragma unroll
    for (int t = 0; t < 2; t++) {
#pragma unroll
        for (int nf = 0; nf < 8; nf++) {
            const int chunk = wh * 8 + nf;
            const int pA = base + t * 16, pB = pA + 8;
            *(uint2*)&gy[((size_t)chunk * HW + pA) * 8 + 2 * kq] =
                make_uint2(split_pack_h(acc[t][nf][0]), split_pack_h(acc[t][nf][1]));
            *(uint2*)&gy[((size_t)chunk * HW + pB) * 8 + 2 * kq] =
                make_uint2(split_pack_h(acc[t][nf][2]), split_pack_h(acc[t][nf][3]));
        }
    }
}

// ============================================================================
// k2: conv3x3 (128->64) + BN + ReLU, fp16 2-pass mma.
// CTA = one image row (256 px) x 64 ch; 9 taps = pixel-shifted accumulating
// GEMMs. NO smem, NO barriers: B via LDG (L1-resident g_wf), A from L2 (g_y).
// ============================================================================
__global__ void __launch_bounds__(256, 2) k2_mma()
{
    const int tid = threadIdx.x, lane = tid & 31, wm = tid >> 5;
    const int y = blockIdx.x, nb = blockIdx.y;
    const int kq = lane & 3, nr = lane >> 2;

    float acc[2][8][4];
#pragma unroll
    for (int t = 0; t < 2; t++)
#pragma unroll
        for (int f = 0; f < 8; f++)
#pragma unroll
            for (int q = 0; q < 4; q++) acc[t][f][q] = 0.f;

    const uint2* Au = (const uint2*)(g_y + (size_t)nb * 16 * HW * 8);
    const uint2* BwL = (const uint2*)g_wf + lane;

#pragma unroll
    for (int tap = 0; tap < 9; tap++) {
        const int dy = tap / 3 - 1, dx = tap % 3 - 1;
        const int gyr = y + dy;
        const bool okY = (unsigned)gyr < (unsigned)Hh;
        int gp[4]; bool vg[4];
#pragma unroll
        for (int g = 0; g < 4; g++) {
            int gx = wm * 32 + g * 8 + nr + dx;
            vg[g] = okY && (unsigned)gx < (unsigned)Ww;
            gp[g] = gyr * Ww + gx;
        }
        const uint2* Bt = BwL + (size_t)tap * 8 * 8 * 32;

#pragma unroll
        for (int ks = 0; ks < 8; ks++) {
            const size_t cA = (size_t)(2 * ks) * HW, cB = cA + HW;
            uint2 q[4][2];
#pragma unroll
            for (int g = 0; g < 4; g++) {
                q[g][0] = vg[g] ? Au[(cA + gp[g]) * 4 + kq] : make_uint2(0u, 0u);
                q[g][1] = vg[g] ? Au[(cB + gp[g]) * 4 + kq] : make_uint2(0u, 0u);
            }
            uint32_t Ahi[2][4], Alo[2][4];
#pragma unroll
            for (int t = 0; t < 2; t++) {
                Ahi[t][0] = hi2(q[2 * t][0]);     Alo[t][0] = lo2(q[2 * t][0]);
                Ahi[t][1] = hi2(q[2 * t + 1][0]); Alo[t][1] = lo2(q[2 * t + 1][0]);
                Ahi[t][2] = hi2(q[2 * t][1]);     Alo[t][2] = lo2(q[2 * t][1]);
                Ahi[t][3] = hi2(q[2 * t + 1][1]); Alo[t][3] = lo2(q[2 * t + 1][1]);
            }
#pragma unroll
            for (int nf = 0; nf < 8; nf++) {
                uint2 b = Bt[(ks * 8 + nf) * 32];
                mma16816h(acc[0][nf], Ahi[0], b.x, b.y);
                mma16816h(acc[0][nf], Alo[0], b.x, b.y);
                mma16816h(acc[1][nf], Ahi[1], b.x, b.y);
                mma16816h(acc[1][nf], Alo[1], b.x, b.y);
            }
        }
    }

    // epilogue: BN + ReLU -> g_x channel-major
    float* Xo = g_x + (size_t)nb * Tc * HW;
#pragma unroll
    for (int t = 0; t < 2; t++) {
        const int op0 = y * Ww + wm * 32 + t * 16 + nr;
        const int op1 = op0 + 8;
#pragma unroll
        for (int nf = 0; nf < 8; nf++) {
            int ch = nf * 8 + 2 * kq;
            float s0 = g_bns[ch], b0 = g_bnb[ch];
            float s1 = g_bns[ch + 1], b1 = g_bnb[ch + 1];
            float r00 = acc[t][nf][0] * s0 + b0; r00 = r00 > 0.f ? r00 : 0.f;
            float r01 = acc[t][nf][1] * s1 + b1; r01 = r01 > 0.f ? r01 : 0.f;
            float r10 = acc[t][nf][2] * s0 + b0; r10 = r10 > 0.f ? r10 : 0.f;
            float r11 = acc[t][nf][3] * s1 + b1; r11 = r11 > 0.f ? r11 : 0.f;
            Xo[(size_t)ch * HW + op0]       = r00;
            Xo[(size_t)(ch + 1) * HW + op0] = r01;
            Xo[(size_t)ch * HW + op1]       = r10;
            Xo[(size_t)(ch + 1) * HW + op1] = r11;
        }
    }
}

// ============================================================================
// k3: conv3x3 (64 -> 2, pad 1) -> flow, channel-split x2 (summed in k4)
// ============================================================================
__global__ void __launch_bounds__(256) k_flowconv(const float* __restrict__ w2)
{
    __shared__ __align__(16) float Xs[8 * 10 * 36];
    __shared__ __align__(16) float Ws[2 * 32 * 9];

    const int bx = blockIdx.x, by = blockIdx.y;
    const int nb = blockIdx.z >> 1, h = blockIdx.z & 1;
    const int tid = threadIdx.x;
    const int py = tid >> 5, px = tid & 31;

    for (int i = tid; i < 2 * 32 * 9; i += 256) {
        int oc = i / 288, c = (i / 9) % 32, tap = i % 9;
        Ws[i] = w2[oc * 576 + (h * 32 + c) * 9 + tap];
    }

    float a0 = 0.f, a1 = 0.f;
    const float* Xb = g_x + ((size_t)nb * Tc + h * 32) * HW;

    for (int c0 = 0; c0 < 32; c0 += 8) {
        for (int i = tid; i < 8 * 10 * 34; i += 256) {
            int cc = i / 340;
            int rem = i - cc * 340;
            int ry = rem / 34, rx = rem - (rem / 34) * 34;
            int gy = by * 8 + ry - 1;
            int gx = bx * 32 + rx - 1;
            float v = 0.f;
            if ((unsigned)gy < (unsigned)Hh && (unsigned)gx < (unsigned)Ww)
                v = Xb[(size_t)(c0 + cc) * HW + gy * Ww + gx];
            Xs[cc * 360 + ry * 36 + rx] = v;
        }
        __syncthreads();
#pragma unroll
        for (int cc = 0; cc < 8; cc++) {
            int c = c0 + cc;
#pragma unroll
            for (int dy = 0; dy < 3; dy++) {
#pragma unroll
                for (int dx = 0; dx < 3; dx++) {
                    float xv = Xs[cc * 360 + (py + dy) * 36 + (px + dx)];
                    int tap = dy * 3 + dx;
                    a0 += Ws[c * 9 + tap] * xv;
                    a1 += Ws[288 + c * 9 + tap] * xv;
                }
            }
        }
        __syncthreads();
    }

    const int oy = by * 8 + py, ox = bx * 32 + px;
    g_flow[h][((size_t)(nb * 2 + 0) * Hh + oy) * Ww + ox] = a0;
    g_flow[h][((size_t)(nb * 2 + 1) * Hh + oy) * Ww + ox] = a1;
}

// ============================================================================
// k4: flow_warp (torch repeat(c,1,1,1) batch-aliasing); sums partial flows
// ============================================================================
__global__ void __launch_bounds__(256) k_warp(
    const float* __restrict__ pred, float* __restrict__ out)
{
    const int idx = blockIdx.x * 256 + threadIdx.x;
    const int x = idx & (Ww - 1);
    const int y = (idx >> 8) & (Hh - 1);
    const int t = idx >> 15;
    const int fb = t & 3;

    const size_t fx_i = ((size_t)(fb * 2 + 0) * Hh + y) * Ww + x;
    const size_t fy_i = ((size_t)(fb * 2 + 1) * Hh + y) * Ww + x;
    const float fx = g_flow[0][fx_i] + g_flow[1][fx_i];
    const float fy = g_flow[0][fy_i] + g_flow[1][fy_i];

    const float gx = -1.f + 2.f * (float)x / (float)(Ww - 1);
    const float gy = -1.f + 2.f * (float)y / (float)(Hh - 1);
    const float sx = gx + fx / (float)Ww;
    const float sy = gy + fy / (float)Hh;
    const float ix = ((sx + 1.f) * (float)Ww - 1.f) * 0.5f;
    const float iy = ((sy + 1.f) * (float)Hh - 1.f) * 0.5f;

    const float x0f = floorf(ix), y0f = floorf(iy);
    const float wx = ix - x0f, wy = iy - y0f;
    const int x0 = (int)x0f, y0 = (int)y0f;

    const float* img = pred + (size_t)t * HW;
    auto samp = [&](int yy, int xx) -> float {
        return (xx >= 0 && xx < Ww && yy >= 0 && yy < Hh) ? img[yy * Ww + xx] : 0.f;
    };
    const float v00 = samp(y0, x0);
    const float v01 = samp(y0, x0 + 1);
    const float v10 = samp(y0 + 1, x0);
    const float v11 = samp(y0 + 1, x0 + 1);

    const float top = v00 * (1.f - wx) + v01 * wx;
    const float bot = v10 * (1.f - wx) + v11 * wx;
    out[idx] = top * (1.f - wy) + bot * wy;
}

// ============================================================================
// launch
// ============================================================================
extern "C" void kernel_launch(void* const* d_in, const int* in_sizes, int n_in,
                              void* d_out, int out_size)
{
    const float* t1_feature = (const float*)d_in[0];
    const float* t2_feature = (const float*)d_in[1];
    const float* t2_pred    = (const float*)d_in[2];
    const float* w_down1    = (const float*)d_in[3];
    const float* w_down2    = (const float*)d_in[4];
    const float* w_flow1    = (const float*)d_in[5];
    const float* bn_gamma   = (const float*)d_in[6];
    const float* bn_beta    = (const float*)d_in[7];
    const float* bn_mean    = (const float*)d_in[8];
    const float* bn_var     = (const float*)d_in[9];
    const float* w_flow2    = (const float*)d_in[10];
    float* out = (float*)d_out;

    k_prep<<<208, 256>>>(w_down1, w_down2, w_flow1, bn_gamma, bn_beta, bn_mean, bn_var);
    k1_mma<<<dim3(128, NB, 2), 256>>>(t1_feature, t2_feature);
    k_probe<<<1, 32>>>();
    k2_mma<<<dim3(Hh, NB), 256>>>();
    k_flowconv<<<dim3(Ww / 32, Hh / 8, NB * 2), 256>>>(w_flow2);
    k_warp<<<(NB * CCLS * HW) / 256, 256>>>(t2_pred, out);
}